// round 8
// baseline (speedup 1.0000x reference)
#include <cuda_runtime.h>
#include <cuda_fp16.h>

// ---------------- problem constants ----------------
#define NBLK 64
#define NTHR 512
#define LPn  128
#define LQn  128
#define Bn   64
#define Hn   150

// ---------------- device scratch ----------------
__device__ float  d_WpE[150 * 152];      // folded Wp, rows padded to 152 (zeros)
__device__ float  d_WqE[150 * 152];      // folded Wq
__device__ float  d_WgU[600 * 152];      // folded Wg (u part), fp32, padded
__device__ __half g_Wv16[150 * 160];     // Wv fp16, rows padded to 160 (zeros)
__device__ __half g_Whh16[450 * 160];    // W_hh fp16
__device__ __half g_WgC16[600 * 160];    // folded Wg (c part) fp16
__device__ __half g_Wih16[450 * 600];    // W_ih fp16 (600 = 75*8, no pad)
__device__ float  d_wup[Bn * LPn * 150]; // [b][i][h]
__device__ float  d_gu[Bn * LPn * 600];  // [b][i][j]
__device__ unsigned g_flags[NBLK];       // monotonic
__device__ unsigned g_rel2;              // monotonic

// ---------------- smem layout (floats) ----------------
#define WUQ_S 0                   // Wuq [l*153 + h]  (128x153 = 19584) ; prologue: UpS [i*152+k]
#define UQT_S 19584               // Uqt [l*152 + d]  (128x152 = 19456)
#define SCR   39040
#define V_S    (SCR + 0)          // 160 (pad zeroed)
#define VB_S   (SCR + 160)        // 152
#define U_S    (SCR + 312)        // 152
#define BSE_S  (SCR + 464)        // 152
#define A_S    (SCR + 616)        // 128
#define AP_S   (SCR + 744)        // 512
#define WVP_S  (SCR + 1256)       // 2*152
#define CCP_S  (SCR + 1560)       // 4*152
#define CC_S   (SCR + 2168)       // 160 (pad zeroed)
#define GH_S   (SCR + 2328)       // 456
#define GHP_S  (SCR + 2784)       // 2*456
#define GU_S   (SCR + 3696)       // 600
#define RG_S   (SCR + 4296)       // 600 (f4-aligned)
#define GI_S   (SCR + 4896)       // 456
#define SMEM_FL (SCR + 5352)      // 44392 floats
#define SMEM_BYTES (SMEM_FL * 4)  // 177568 B

// ---------------- helpers ----------------
__device__ __forceinline__ float warp_max_all(float v) {
#pragma unroll
    for (int o = 16; o > 0; o >>= 1) v = fmaxf(v, __shfl_xor_sync(0xffffffffu, v, o));
    return v;
}
__device__ __forceinline__ float warp_sum_all(float v) {
#pragma unroll
    for (int o = 16; o > 0; o >>= 1) v += __shfl_xor_sync(0xffffffffu, v, o);
    return v;
}
__device__ __forceinline__ float fast_sig(float x) {
    return 1.0f / (1.0f + __expf(-x));
}
__device__ __forceinline__ float fast_tanh(float x) {   // precise path (GRU)
    float cx = fminf(fmaxf(x, -15.0f), 15.0f);
    float e  = __expf(2.0f * cx);
    return __fdividef(e - 1.0f, e + 1.0f);
}
__device__ __forceinline__ float tanh_fastest(float x) { // attention path
    float y;
    asm("tanh.approx.f32 %0, %1;" : "=f"(y) : "f"(x));
    return y;
}

// fp16-row x fp32-smem dot, 8 accumulators, nq uint4 (8 halfs each).
// All lanes typically share x (broadcast LDS), each lane has its own row (coalesced LDG).
__device__ __forceinline__ float dot_h(const __half* __restrict__ row,
                                       const float* __restrict__ x, int nq) {
    const uint4* r4 = (const uint4*)row;
    float a0 = 0.f, a1 = 0.f, a2 = 0.f, a3 = 0.f;
    float a4 = 0.f, a5 = 0.f, a6 = 0.f, a7 = 0.f;
#pragma unroll 5
    for (int q = 0; q < nq; q++) {
        uint4 u = r4[q];
        float2 f0 = __half22float2(*(__half2*)&u.x);
        float2 f1 = __half22float2(*(__half2*)&u.y);
        float2 f2 = __half22float2(*(__half2*)&u.z);
        float2 f3 = __half22float2(*(__half2*)&u.w);
        const float* xp = x + q * 8;
        a0 += f0.x * xp[0]; a1 += f0.y * xp[1];
        a2 += f1.x * xp[2]; a3 += f1.y * xp[3];
        a4 += f2.x * xp[4]; a5 += f2.y * xp[5];
        a6 += f3.x * xp[6]; a7 += f3.y * xp[7];
    }
    return ((a0 + a1) + (a2 + a3)) + ((a4 + a5) + (a6 + a7));
}

// Flag-array grid barrier (prologue only). Monotonic, atomic-free.
__device__ __forceinline__ void gsync(unsigned& gen) {
    __syncthreads();
    const unsigned target = gen + 1u;
    if (blockIdx.x == 0) {
        if (threadIdx.x < 32) {
            const int ln = threadIdx.x;
            if (ln == 0) *((volatile unsigned*)&g_flags[0]) = target;
            bool ok;
            do {
                unsigned f0, f1;
                asm volatile("ld.acquire.gpu.u32 %0, [%1];" : "=r"(f0) : "l"(&g_flags[ln]));
                asm volatile("ld.acquire.gpu.u32 %0, [%1];" : "=r"(f1) : "l"(&g_flags[ln + 32]));
                ok = (f0 >= target) & (f1 >= target);
            } while (!__all_sync(0xffffffffu, ok));
            if (ln == 0)
                asm volatile("st.release.gpu.u32 [%0], %1;" :: "l"(&g_rel2), "r"(target) : "memory");
        }
    } else {
        if (threadIdx.x == 0) {
            asm volatile("st.release.gpu.u32 [%0], %1;"
                         :: "l"(&g_flags[blockIdx.x]), "r"(target) : "memory");
            unsigned r;
            do {
                asm volatile("ld.acquire.gpu.u32 %0, [%1];" : "=r"(r) : "l"(&g_rel2));
            } while (r < target);
        }
    }
    gen = target;
    __syncthreads();
}

// ---------------- the persistent kernel: one block per batch ----------------
__global__ void __launch_bounds__(NTHR, 1) pqm_kernel(
    const float* __restrict__ Up, const float* __restrict__ Uq,
    const float* __restrict__ Wp, const float* __restrict__ Wq,
    const float* __restrict__ Wv, const float* __restrict__ Wg,
    const float* __restrict__ Vmat, const float* __restrict__ v0,
    const float* __restrict__ W_ih, const float* __restrict__ W_hh,
    const float* __restrict__ b_ih, const float* __restrict__ b_hh,
    float* __restrict__ out)
{
    extern __shared__ float sm[];
    const int tid = threadIdx.x;
    const int b   = blockIdx.x;          // this block owns batch b

    unsigned gen = *((volatile unsigned*)&g_rel2);

    // ======== P0: fold + fp16 conversion of all shared weights ========
    const int gid = b * NTHR + tid;
    for (int idx = gid; idx < 150 * 152; idx += NBLK * NTHR) {
        int h = idx / 152, d = idx - h * 152;
        d_WpE[idx] = (d < 150) ? Wp[h * 300 + d] + Wp[h * 300 + 150 + d] : 0.f;
        d_WqE[idx] = (d < 150) ? Wq[h * 300 + d] + Wq[h * 300 + 150 + d] : 0.f;
    }
    for (int idx = gid; idx < 600 * 152; idx += NBLK * NTHR) {
        int j = idx / 152, k = idx - j * 152;
        d_WgU[idx] = (k < 150) ? Wg[j * 600 + k] + Wg[j * 600 + 150 + k] : 0.f;
    }
    for (int idx = gid; idx < 600 * 160; idx += NBLK * NTHR) {
        int j = idx / 160, k = idx - j * 160;
        g_WgC16[idx] = __float2half_rn((k < 150) ? Wg[j * 600 + 300 + k] + Wg[j * 600 + 450 + k] : 0.f);
    }
    for (int idx = gid; idx < 150 * 160; idx += NBLK * NTHR) {
        int h = idx / 160, k = idx - h * 160;
        g_Wv16[idx] = __float2half_rn((k < 150) ? Wv[h * 150 + k] : 0.f);
    }
    for (int idx = gid; idx < 450 * 160; idx += NBLK * NTHR) {
        int j = idx / 160, k = idx - j * 160;
        g_Whh16[idx] = __float2half_rn((k < 150) ? W_hh[j * 150 + k] : 0.f);
    }
    for (int idx = gid; idx < 450 * 600; idx += NBLK * NTHR)
        g_Wih16[idx] = __float2half_rn(W_ih[idx]);
    gsync(gen);   // the ONLY grid barrier

    // ======== P1 (block-local): per-batch precompute ========
    {
        float* A = sm + WUQ_S;   // first: UpS [i*152 + k]
        float* B = sm + UQT_S;   // Uqt   [l*152 + d]
        // stage Up[.][b]
        for (int t = tid; t < 128 * 150; t += NTHR) {
            int i = t / 150, k = t - i * 150;
            A[i * 152 + k] = Up[(i * Bn + b) * 150 + k];
        }
        __syncthreads();
        // gu[i][j] = Up[i][b] @ WgU^T   (tasks: it-of-8 x j)
        for (int task = tid; task < 16 * 600; task += NTHR) {
            int j = task % 600, it = task / 600;
            float acc[8] = {0.f, 0.f, 0.f, 0.f, 0.f, 0.f, 0.f, 0.f};
            const float4* wr = (const float4*)(d_WgU + j * 152);
            for (int q = 0; q < 38; q++) {
                float4 w4 = wr[q];
#pragma unroll
                for (int ii = 0; ii < 8; ii++) {
                    const float* xr = A + (it * 8 + ii) * 152 + q * 4;
                    acc[ii] += w4.x * xr[0] + w4.y * xr[1] + w4.z * xr[2] + w4.w * xr[3];
                }
            }
#pragma unroll
            for (int ii = 0; ii < 8; ii++)
                d_gu[(b * LPn + it * 8 + ii) * 600 + j] = acc[ii];
        }
        // wup[i][h] = Up[i][b] @ WpE^T
        for (int task = tid; task < 16 * 150; task += NTHR) {
            int h = task % 150, it = task / 150;
            float acc[8] = {0.f, 0.f, 0.f, 0.f, 0.f, 0.f, 0.f, 0.f};
            const float4* wr = (const float4*)(d_WpE + h * 152);
            for (int q = 0; q < 38; q++) {
                float4 w4 = wr[q];
#pragma unroll
                for (int ii = 0; ii < 8; ii++) {
                    const float* xr = A + (it * 8 + ii) * 152 + q * 4;
                    acc[ii] += w4.x * xr[0] + w4.y * xr[1] + w4.z * xr[2] + w4.w * xr[3];
                }
            }
#pragma unroll
            for (int ii = 0; ii < 8; ii++)
                d_wup[(b * LPn + it * 8 + ii) * 150 + h] = acc[ii];
        }
        __syncthreads();   // done with A = UpS
        // stage Uqt [l][d]
        for (int t = tid; t < 128 * 150; t += NTHR) {
            int l = t / 150, d = t - l * 150;
            B[l * 152 + d] = Uq[(l * Bn + b) * 150 + d];
        }
        __syncthreads();
        // Wuq[l][h] = Uq[l][b] @ WqE^T  -> A with stride 153 (conflict-free for s-loop)
        for (int task = tid; task < 16 * 150; task += NTHR) {
            int h = task % 150, lt = task / 150;
            float acc[8] = {0.f, 0.f, 0.f, 0.f, 0.f, 0.f, 0.f, 0.f};
            const float4* wr = (const float4*)(d_WqE + h * 152);
            for (int q = 0; q < 38; q++) {
                float4 w4 = wr[q];
#pragma unroll
                for (int ii = 0; ii < 8; ii++) {
                    const float* xr = B + (lt * 8 + ii) * 152 + q * 4;
                    acc[ii] += w4.x * xr[0] + w4.y * xr[1] + w4.z * xr[2] + w4.w * xr[3];
                }
            }
#pragma unroll
            for (int ii = 0; ii < 8; ii++)
                A[(lt * 8 + ii) * 153 + h] = acc[ii];
        }
        // init v_s, V row, zero pads
        if (tid < 150) {
            sm[V_S + tid]  = v0[b * 150 + tid];
            sm[VB_S + tid] = Vmat[b * 150 + tid];
        }
        if (tid >= 150 && tid < 160) {
            sm[V_S + tid]  = 0.f;
            sm[CC_S + tid] = 0.f;
        }
    }
    __syncthreads();

    const float* WUQ = sm + WUQ_S;
    const float* UQT = sm + UQT_S;
    const int w = tid >> 5, ln = tid & 31;

    // ======== main scan: 128 steps, block-local, zero grid barriers ========
    for (int i = 0; i < LPn; i++) {
        // S1: wv partials (300 thr) | stage u_s, bse<-wup, gu_s (212 thr)
        if (tid < 300) {
            int g = tid / 150, h = tid - g * 150;
            sm[WVP_S + g * 152 + h] =
                dot_h(g_Wv16 + h * 160 + g * 80, sm + V_S + g * 80, 10);
        } else {
            for (int task = tid - 300; task < 900; task += 212) {
                if (task < 150)      sm[U_S + task]         = Up[(i * Bn + b) * 150 + task];
                else if (task < 300) sm[BSE_S + task - 150] = d_wup[(b * LPn + i) * 150 + task - 150];
                else                 sm[GU_S + task - 300]  = d_gu[(b * LPn + i) * 600 + task - 300];
            }
        }
        __syncthreads();
        // S2: combine bse
        if (tid < 150) sm[BSE_S + tid] += sm[WVP_S + tid] + sm[WVP_S + 152 + tid];
        __syncthreads();
        // S3: s[l] partials over k-quarters (all 512)
        {
            int l = tid & 127, g = tid >> 7;
            int k0 = (g * 150) >> 2, k1 = ((g + 1) * 150) >> 2;
            const float* wq = WUQ + l * 153;
            float acc = 0.f;
#pragma unroll 10
            for (int k = k0; k < k1; k++)
                acc += tanh_fastest(sm[BSE_S + k] + wq[k]) * sm[VB_S + k];
            sm[AP_S + g * 128 + l] = acc;
        }
        __syncthreads();
        // S4: warp0 softmax | warps 1-15: gh partials (900 tasks)
        if (w == 0) {
            float a0 = sm[AP_S + ln]      + sm[AP_S + 128 + ln]      + sm[AP_S + 256 + ln]      + sm[AP_S + 384 + ln];
            float a1 = sm[AP_S + ln + 32] + sm[AP_S + 160 + ln]      + sm[AP_S + 288 + ln]      + sm[AP_S + 416 + ln];
            float a2 = sm[AP_S + ln + 64] + sm[AP_S + 192 + ln]      + sm[AP_S + 320 + ln]      + sm[AP_S + 448 + ln];
            float a3 = sm[AP_S + ln + 96] + sm[AP_S + 224 + ln]      + sm[AP_S + 352 + ln]      + sm[AP_S + 480 + ln];
            float m = fmaxf(fmaxf(a0, a1), fmaxf(a2, a3));
            m = warp_max_all(m);
            float e0 = __expf(a0 - m), e1 = __expf(a1 - m);
            float e2 = __expf(a2 - m), e3 = __expf(a3 - m);
            float ssum = warp_sum_all(e0 + e1 + e2 + e3);
            float inv = __fdividef(1.0f, ssum);
            sm[A_S + ln] = e0 * inv; sm[A_S + ln + 32] = e1 * inv;
            sm[A_S + ln + 64] = e2 * inv; sm[A_S + ln + 96] = e3 * inv;
        } else {
            for (int task = tid - 32; task < 900; task += 480) {
                int j = task % 450, g = task / 450;
                sm[GHP_S + g * 456 + j] =
                    dot_h(g_Whh16 + j * 160 + g * 80, sm + V_S + g * 80, 10);
            }
        }
        __syncthreads();
        // S5: cc partials (600) + gh combine (450)
        for (int task = tid; task < 1050; task += NTHR) {
            if (task < 600) {
                int d = task % 150, lq = task / 150;
                const float* uq = UQT + (lq * 32) * 152 + d;
                const float* av = sm + A_S + lq * 32;
                float acc = 0.f;
#pragma unroll
                for (int t = 0; t < 32; t++) acc += av[t] * uq[t * 152];
                sm[CCP_S + lq * 152 + d] = acc;
            } else {
                int j = task - 600;
                sm[GH_S + j] = b_hh[j] + sm[GHP_S + j] + sm[GHP_S + 456 + j];
            }
        }
        __syncthreads();
        // S6a: cc combine
        if (tid < 150)
            sm[CC_S + tid] = sm[CCP_S + tid] + sm[CCP_S + 152 + tid]
                           + sm[CCP_S + 304 + tid] + sm[CCP_S + 456 + tid];
        __syncthreads();
        // S6b: B: rg[j] = sig(gu[j] + cc@WgC_j) * rbase
        for (int j = tid; j < 600; j += NTHR) {
            float g = sm[GU_S + j] + dot_h(g_WgC16 + j * 160, sm + CC_S, 20);
            float sg = fast_sig(g);
            int km = (j < 150) ? j : (j < 300) ? j - 150 : (j < 450) ? j - 300 : j - 450;
            float rb = (j < 300) ? sm[U_S + km] : sm[CC_S + km];
            sm[RG_S + j] = sg * rb;
        }
        __syncthreads();
        // S7: C: gi[j] = b_ih[j] + rg @ Wih_j
        for (int j = tid; j < 450; j += NTHR)
            sm[GI_S + j] = b_ih[j] + dot_h(g_Wih16 + j * 600, sm + RG_S, 75);
        __syncthreads();
        // S8: GRU combine, write out + v_s
        if (tid < 150) {
            int h = tid;
            float r_ = fast_sig(sm[GI_S + h]       + sm[GH_S + h]);
            float z_ = fast_sig(sm[GI_S + 150 + h] + sm[GH_S + 150 + h]);
            float n_ = fast_tanh(sm[GI_S + 300 + h] + r_ * sm[GH_S + 300 + h]);
            float hnew = (1.0f - z_) * n_ + z_ * sm[V_S + h];
            out[(i * Bn + b) * 150 + h] = hnew;
            sm[V_S + h] = hnew;
        }
        __syncthreads();
    }
}

// ---------------- launch ----------------
extern "C" void kernel_launch(void* const* d_in, const int* in_sizes, int n_in,
                              void* d_out, int out_size)
{
    const float* Up   = (const float*)d_in[0];
    const float* Uq   = (const float*)d_in[1];
    const float* Wp   = (const float*)d_in[2];
    const float* Wq   = (const float*)d_in[3];
    const float* Wv   = (const float*)d_in[4];
    const float* Wg   = (const float*)d_in[5];
    const float* Vm   = (const float*)d_in[6];
    const float* v0   = (const float*)d_in[7];
    const float* W_ih = (const float*)d_in[8];
    const float* W_hh = (const float*)d_in[9];
    const float* b_ih = (const float*)d_in[10];
    const float* b_hh = (const float*)d_in[11];
    float* out = (float*)d_out;

    cudaFuncSetAttribute(pqm_kernel, cudaFuncAttributeMaxDynamicSharedMemorySize, SMEM_BYTES);
    pqm_kernel<<<NBLK, NTHR, SMEM_BYTES>>>(Up, Uq, Wp, Wq, Wv, Wg, Vm, v0,
                                           W_ih, W_hh, b_ih, b_hh, out);
}

// round 9
// speedup vs baseline: 2.0840x; 2.0840x over previous
#include <cuda_runtime.h>
#include <cuda_fp16.h>

// ---------------- problem constants ----------------
#define NBLK 64
#define NTHR 1024
#define LPn  128
#define Bn   64

// ---------------- device scratch ----------------
__device__ float  d_WpE[150 * 152];      // folded Wp (row pad zeros)
__device__ float  d_WqE[150 * 152];      // folded Wq
__device__ float  d_WgU[600 * 152];      // folded Wg (u part)
__device__ __half g_WvT [150 * 160];     // Wv^T   [k][j] fp16 (j pad zeros)
__device__ __half g_WhhT[150 * 464];     // W_hh^T [k][j]
__device__ __half g_WgCT[150 * 600];     // folded Wg(c)^T [k][j]
__device__ __half g_WihT[600 * 464];     // W_ih^T [k][j]
__device__ float  d_wup[Bn * LPn * 150]; // [b][i][h]
__device__ float  d_gu [Bn * LPn * 600]; // [b][i][j]
__device__ unsigned g_flags[NBLK];       // monotonic
__device__ unsigned g_rel2;              // monotonic

// ---------------- smem layout (floats) ----------------
#define WUQ_S  0                      // Wuq fp32 [l*153+h] (128x153=19584); P1: Up staging
#define UQH_S  19584                  // Uqt fp16 [l*152+d] = 19456 halfs = 9728 floats
#define SCR    29312
#define V_S    (SCR + 0)              // 152
#define VB_S   (SCR + 152)            // 152
#define U_S    (SCR + 304)            // 152
#define BSE_S  (SCR + 456)            // 152
#define CC_S   (SCR + 608)            // 152
#define A_S    (SCR + 760)            // 128
#define GU_S   (SCR + 888)            // 600
#define RG_S   (SCR + 1488)           // 600
#define GH_S   (SCR + 2088)           // 456
#define AP_S   (SCR + 3000)           // 1024   (P1: Uq staging 64x152=9728 from here)
#define WVP_S  (SCR + 4024)           // 8 x 160
#define GHP_S  (SCR + 5304)           // 8 x 464
#define CCP_S  (SCR + 9016)           // 8 x 152
#define BP_S   (SCR + 10232)          // 10 x 600
#define CP_S   (SCR + 16232)          // 16 x 464
#define SMEM_FL (SCR + 23656)         // 52968 floats
#define SMEM_BYTES (SMEM_FL * 4)      // 211872 B

// ---------------- helpers ----------------
__device__ __forceinline__ float warp_max_all(float v) {
#pragma unroll
    for (int o = 16; o > 0; o >>= 1) v = fmaxf(v, __shfl_xor_sync(0xffffffffu, v, o));
    return v;
}
__device__ __forceinline__ float warp_sum_all(float v) {
#pragma unroll
    for (int o = 16; o > 0; o >>= 1) v += __shfl_xor_sync(0xffffffffu, v, o);
    return v;
}
__device__ __forceinline__ float fast_sig(float x) {
    return 1.0f / (1.0f + __expf(-x));
}
__device__ __forceinline__ float fast_tanh(float x) {   // precise path (GRU)
    float cx = fminf(fmaxf(x, -15.0f), 15.0f);
    float e  = __expf(2.0f * cx);
    return __fdividef(e - 1.0f, e + 1.0f);
}
__device__ __forceinline__ float tanh_fastest(float x) { // attention path
    float y;
    asm("tanh.approx.f32 %0, %1;" : "=f"(y) : "f"(x));
    return y;
}

// 8 MACs: one uint4 = 8 fp16 weights (8 consecutive j), one broadcast x
__device__ __forceinline__ void fma8(float acc[8], uint4 u, float xk) {
    float2 f0 = __half22float2(*(__half2*)&u.x);
    float2 f1 = __half22float2(*(__half2*)&u.y);
    float2 f2 = __half22float2(*(__half2*)&u.z);
    float2 f3 = __half22float2(*(__half2*)&u.w);
    acc[0] += f0.x * xk; acc[1] += f0.y * xk;
    acc[2] += f1.x * xk; acc[3] += f1.y * xk;
    acc[4] += f2.x * xk; acc[5] += f2.y * xk;
    acc[6] += f3.x * xk; acc[7] += f3.y * xk;
}
__device__ __forceinline__ void st8(float* dst, const float acc[8]) {
    float4* d4 = (float4*)dst;
    d4[0] = make_float4(acc[0], acc[1], acc[2], acc[3]);
    d4[1] = make_float4(acc[4], acc[5], acc[6], acc[7]);
}

// Flag-array grid barrier (prologue only). Monotonic, atomic-free.
__device__ __forceinline__ void gsync(unsigned& gen) {
    __syncthreads();
    const unsigned target = gen + 1u;
    if (blockIdx.x == 0) {
        if (threadIdx.x < 32) {
            const int ln = threadIdx.x;
            if (ln == 0) *((volatile unsigned*)&g_flags[0]) = target;
            bool ok;
            do {
                unsigned f0, f1;
                asm volatile("ld.acquire.gpu.u32 %0, [%1];" : "=r"(f0) : "l"(&g_flags[ln]));
                asm volatile("ld.acquire.gpu.u32 %0, [%1];" : "=r"(f1) : "l"(&g_flags[ln + 32]));
                ok = (f0 >= target) & (f1 >= target);
            } while (!__all_sync(0xffffffffu, ok));
            if (ln == 0)
                asm volatile("st.release.gpu.u32 [%0], %1;" :: "l"(&g_rel2), "r"(target) : "memory");
        }
    } else {
        if (threadIdx.x == 0) {
            asm volatile("st.release.gpu.u32 [%0], %1;"
                         :: "l"(&g_flags[blockIdx.x]), "r"(target) : "memory");
            unsigned r;
            do {
                asm volatile("ld.acquire.gpu.u32 %0, [%1];" : "=r"(r) : "l"(&g_rel2));
            } while (r < target);
        }
    }
    gen = target;
    __syncthreads();
}

// ---------------- the persistent kernel: one block per batch ----------------
__global__ void __launch_bounds__(NTHR, 1) pqm_kernel(
    const float* __restrict__ Up, const float* __restrict__ Uq,
    const float* __restrict__ Wp, const float* __restrict__ Wq,
    const float* __restrict__ Wv, const float* __restrict__ Wg,
    const float* __restrict__ Vmat, const float* __restrict__ v0,
    const float* __restrict__ W_ih, const float* __restrict__ W_hh,
    const float* __restrict__ b_ih, const float* __restrict__ b_hh,
    float* __restrict__ out)
{
    extern __shared__ float sm[];
    __half* UQH = (__half*)(sm + UQH_S);
    const int tid = threadIdx.x;
    const int b   = blockIdx.x;
    const int w   = tid >> 5, ln = tid & 31;

    unsigned gen = *((volatile unsigned*)&g_rel2);

    // ======== P0: folds + TRANSPOSED fp16 weight builds ========
    const int gid = b * NTHR + tid;
    const int gstride = NBLK * NTHR;
    for (int idx = gid; idx < 150 * 152; idx += gstride) {
        int h = idx / 152, d = idx - h * 152;
        d_WpE[idx] = (d < 150) ? Wp[h * 300 + d] + Wp[h * 300 + 150 + d] : 0.f;
        d_WqE[idx] = (d < 150) ? Wq[h * 300 + d] + Wq[h * 300 + 150 + d] : 0.f;
    }
    for (int idx = gid; idx < 600 * 152; idx += gstride) {
        int j = idx / 152, k = idx - j * 152;
        d_WgU[idx] = (k < 150) ? Wg[j * 600 + k] + Wg[j * 600 + 150 + k] : 0.f;
    }
    for (int idx = gid; idx < 150 * 160; idx += gstride) {
        int k = idx / 160, j = idx - k * 160;
        g_WvT[idx] = __float2half_rn((j < 150) ? Wv[j * 150 + k] : 0.f);
    }
    for (int idx = gid; idx < 150 * 464; idx += gstride) {
        int k = idx / 464, j = idx - k * 464;
        g_WhhT[idx] = __float2half_rn((j < 450) ? W_hh[j * 150 + k] : 0.f);
    }
    for (int idx = gid; idx < 150 * 600; idx += gstride) {
        int k = idx / 600, j = idx - k * 600;
        g_WgCT[idx] = __float2half_rn(Wg[j * 600 + 300 + k] + Wg[j * 600 + 450 + k]);
    }
    for (int idx = gid; idx < 600 * 464; idx += gstride) {
        int k = idx / 464, j = idx - k * 464;
        g_WihT[idx] = __float2half_rn((j < 450) ? W_ih[j * 600 + k] : 0.f);
    }
    gsync(gen);   // the ONLY grid barrier

    // ======== P1 (block-local): per-batch precompute ========
    {
        float* A = sm + WUQ_S;     // Up staging [i*152+k]
        for (int t = tid; t < 128 * 150; t += NTHR) {
            int ii = t / 150, k = t - ii * 150;
            A[ii * 152 + k] = Up[(ii * Bn + b) * 150 + k];
        }
        __syncthreads();
        // gu[i][j] = Up[i] @ WgU^T
        for (int task = tid; task < 16 * 600; task += NTHR) {
            int j = task % 600, it = task / 600;
            float acc[8] = {0.f, 0.f, 0.f, 0.f, 0.f, 0.f, 0.f, 0.f};
            const float4* wr = (const float4*)(d_WgU + j * 152);
            for (int q = 0; q < 38; q++) {
                float4 w4 = wr[q];
#pragma unroll
                for (int ii = 0; ii < 8; ii++) {
                    const float* xr = A + (it * 8 + ii) * 152 + q * 4;
                    acc[ii] += w4.x * xr[0] + w4.y * xr[1] + w4.z * xr[2] + w4.w * xr[3];
                }
            }
#pragma unroll
            for (int ii = 0; ii < 8; ii++)
                d_gu[(b * LPn + it * 8 + ii) * 600 + j] = acc[ii];
        }
        // wup[i][h] = Up[i] @ WpE^T
        for (int task = tid; task < 16 * 150; task += NTHR) {
            int h = task % 150, it = task / 150;
            float acc[8] = {0.f, 0.f, 0.f, 0.f, 0.f, 0.f, 0.f, 0.f};
            const float4* wr = (const float4*)(d_WpE + h * 152);
            for (int q = 0; q < 38; q++) {
                float4 w4 = wr[q];
#pragma unroll
                for (int ii = 0; ii < 8; ii++) {
                    const float* xr = A + (it * 8 + ii) * 152 + q * 4;
                    acc[ii] += w4.x * xr[0] + w4.y * xr[1] + w4.z * xr[2] + w4.w * xr[3];
                }
            }
#pragma unroll
            for (int ii = 0; ii < 8; ii++)
                d_wup[(b * LPn + it * 8 + ii) * 150 + h] = acc[ii];
        }
        __syncthreads();
        // Uq in two halves: stage fp32 (scratch) + fp16 (UQH), compute Wuq -> WUQ_S
        float* S2 = sm + AP_S;   // 64x152 staging (scratch region, P1 only)
        for (int ph = 0; ph < 2; ph++) {
            for (int t = tid; t < 64 * 150; t += NTHR) {
                int ll = t / 150, d = t - ll * 150;
                float vv = Uq[((ph * 64 + ll) * Bn + b) * 150 + d];
                S2[ll * 152 + d] = vv;
                UQH[(ph * 64 + ll) * 152 + d] = __float2half_rn(vv);
            }
            __syncthreads();
            for (int task = tid; task < 8 * 150; task += NTHR) {
                int h = task % 150, lt = task / 150;
                float acc[8] = {0.f, 0.f, 0.f, 0.f, 0.f, 0.f, 0.f, 0.f};
                const float4* wr = (const float4*)(d_WqE + h * 152);
                for (int q = 0; q < 38; q++) {
                    float4 w4 = wr[q];
#pragma unroll
                    for (int ii = 0; ii < 8; ii++) {
                        const float* xr = S2 + (lt * 8 + ii) * 152 + q * 4;
                        acc[ii] += w4.x * xr[0] + w4.y * xr[1] + w4.z * xr[2] + w4.w * xr[3];
                    }
                }
#pragma unroll
                for (int ii = 0; ii < 8; ii++)
                    sm[WUQ_S + (ph * 64 + lt * 8 + ii) * 153 + h] = acc[ii];
            }
            __syncthreads();
        }
        if (tid < 150) {
            sm[V_S + tid]  = v0[b * 150 + tid];
            sm[VB_S + tid] = Vmat[b * 150 + tid];
        }
    }
    __syncthreads();

    // ======== main scan: 128 steps, block-local ========
    for (int i = 0; i < LPn; i++) {
        // ---- Stage A: wv (w 0-7) | gh (w 8-23) | per-step loads (w 24-31) ----
        if (w < 8) {
            int k0 = (w * 150) >> 3, k1 = ((w + 1) * 150) >> 3;
            if (ln < 20) {
                float acc[8] = {0.f, 0.f, 0.f, 0.f, 0.f, 0.f, 0.f, 0.f};
                const uint4* base = (const uint4*)g_WvT;   // 20 uint4/row
#pragma unroll 4
                for (int k = k0; k < k1; k++) fma8(acc, base[k * 20 + ln], sm[V_S + k]);
                st8(sm + WVP_S + w * 160 + 8 * ln, acc);
            }
        } else if (w < 24) {
            int wl = w - 8, kg = wl >> 1, jg = wl & 1;
            int k0 = (kg * 150) >> 3, k1 = ((kg + 1) * 150) >> 3;
            if (ln < 29) {
                float acc[8] = {0.f, 0.f, 0.f, 0.f, 0.f, 0.f, 0.f, 0.f};
                const uint4* base = (const uint4*)g_WhhT;  // 58 uint4/row
                int off = jg * 29 + ln;
#pragma unroll 4
                for (int k = k0; k < k1; k++) fma8(acc, base[k * 58 + off], sm[V_S + k]);
                st8(sm + GHP_S + kg * 464 + jg * 232 + 8 * ln, acc);
            }
        } else {
            for (int t = tid - 768; t < 900; t += 256) {
                if (t < 150)      sm[U_S + t]         = Up[(i * Bn + b) * 150 + t];
                else if (t < 300) sm[BSE_S + t - 150] = d_wup[(b * LPn + i) * 150 + t - 150];
                else              sm[GU_S + t - 300]  = d_gu[(b * LPn + i) * 600 + t - 300];
            }
        }
        __syncthreads();
        // ---- combine: bse (150) + gh (450) ----
        for (int t = tid; t < 600; t += NTHR) {
            if (t < 150) {
                float s = sm[BSE_S + t];
#pragma unroll
                for (int g = 0; g < 8; g++) s += sm[WVP_S + g * 160 + t];
                sm[BSE_S + t] = s;
            } else {
                int j = t - 150;
                float s = b_hh[j];
#pragma unroll
                for (int g = 0; g < 8; g++) s += sm[GHP_S + g * 464 + j];
                sm[GH_S + j] = s;
            }
        }
        __syncthreads();
        // ---- S3: s[l] partials (128 l x 8 k-groups = 1024 tasks) ----
        {
            int l = tid & 127, g = tid >> 7;
            int k0 = (g * 150) >> 3, k1 = ((g + 1) * 150) >> 3;
            const float* wq = sm + WUQ_S + l * 153;
            float acc = 0.f;
#pragma unroll 10
            for (int k = k0; k < k1; k++)
                acc += tanh_fastest(sm[BSE_S + k] + wq[k]) * sm[VB_S + k];
            sm[AP_S + g * 128 + l] = acc;
        }
        __syncthreads();
        // ---- softmax (warp 0) ----
        if (w == 0) {
            float a0 = 0.f, a1 = 0.f, a2 = 0.f, a3 = 0.f;
#pragma unroll
            for (int g = 0; g < 8; g++) {
                const float* apg = sm + AP_S + g * 128;
                a0 += apg[ln]; a1 += apg[32 + ln]; a2 += apg[64 + ln]; a3 += apg[96 + ln];
            }
            float m = fmaxf(fmaxf(a0, a1), fmaxf(a2, a3));
            m = warp_max_all(m);
            float e0 = __expf(a0 - m), e1 = __expf(a1 - m);
            float e2 = __expf(a2 - m), e3 = __expf(a3 - m);
            float ssum = warp_sum_all(e0 + e1 + e2 + e3);
            float inv = __fdividef(1.0f, ssum);
            sm[A_S + ln] = e0 * inv; sm[A_S + 32 + ln] = e1 * inv;
            sm[A_S + 64 + ln] = e2 * inv; sm[A_S + 96 + ln] = e3 * inv;
        }
        __syncthreads();
        // ---- cc partials (8 l-groups x 150 d = 1200 tasks) ----
        for (int t = tid; t < 1200; t += NTHR) {
            int lq = t / 150, d = t - lq * 150;
            const __half* uq = UQH + lq * 16 * 152 + d;
            const float* av = sm + A_S + lq * 16;
            float acc = 0.f;
#pragma unroll
            for (int q = 0; q < 16; q++) acc += av[q] * __half2float(uq[q * 152]);
            sm[CCP_S + lq * 152 + d] = acc;
        }
        __syncthreads();
        if (tid < 150) {
            float s = 0.f;
#pragma unroll
            for (int g = 0; g < 8; g++) s += sm[CCP_S + g * 152 + tid];
            sm[CC_S + tid] = s;
        }
        __syncthreads();
        // ---- B partials: 10 kg x 3 jg (w 0-29) ----
        if (w < 30 && ln < 25) {
            int kg = w / 3, jg = w - kg * 3;
            int k0 = kg * 15;
            float acc[8] = {0.f, 0.f, 0.f, 0.f, 0.f, 0.f, 0.f, 0.f};
            const uint4* base = (const uint4*)g_WgCT;      // 75 uint4/row
            int off = jg * 25 + ln;
#pragma unroll 5
            for (int k = k0; k < k0 + 15; k++) fma8(acc, base[k * 75 + off], sm[CC_S + k]);
            st8(sm + BP_S + kg * 600 + jg * 200 + 8 * ln, acc);
        }
        __syncthreads();
        // ---- B combine: rg ----
        for (int j = tid; j < 600; j += NTHR) {
            float g = sm[GU_S + j];
#pragma unroll
            for (int q = 0; q < 10; q++) g += sm[BP_S + q * 600 + j];
            float sg = fast_sig(g);
            int km = (j < 150) ? j : (j < 300) ? j - 150 : (j < 450) ? j - 300 : j - 450;
            float rb = (j < 300) ? sm[U_S + km] : sm[CC_S + km];
            sm[RG_S + j] = sg * rb;
        }
        __syncthreads();
        // ---- C partials: 16 kg x 2 jg (all 32 warps) ----
        {
            int kg = w >> 1, jg = w & 1;
            int k0 = (kg * 600) >> 4, k1 = ((kg + 1) * 600) >> 4;
            if (ln < 29) {
                float acc[8] = {0.f, 0.f, 0.f, 0.f, 0.f, 0.f, 0.f, 0.f};
                const uint4* base = (const uint4*)g_WihT;  // 58 uint4/row
                int off = jg * 29 + ln;
#pragma unroll 4
                for (int k = k0; k < k1; k++) fma8(acc, base[k * 58 + off], sm[RG_S + k]);
                st8(sm + CP_S + kg * 464 + jg * 232 + 8 * ln, acc);
            }
        }
        __syncthreads();
        // ---- GRU combine (150 threads) ----
        if (tid < 150) {
            int h = tid;
            float ir = b_ih[h], iz = b_ih[150 + h], in_ = b_ih[300 + h];
#pragma unroll
            for (int g = 0; g < 16; g++) {
                const float* cp = sm + CP_S + g * 464;
                ir += cp[h]; iz += cp[150 + h]; in_ += cp[300 + h];
            }
            float r_ = fast_sig(ir + sm[GH_S + h]);
            float z_ = fast_sig(iz + sm[GH_S + 150 + h]);
            float n_ = fast_tanh(in_ + r_ * sm[GH_S + 300 + h]);
            float hnew = (1.0f - z_) * n_ + z_ * sm[V_S + h];
            out[(i * Bn + b) * 150 + h] = hnew;
            sm[V_S + h] = hnew;
        }
        __syncthreads();
    }
}

// ---------------- launch ----------------
extern "C" void kernel_launch(void* const* d_in, const int* in_sizes, int n_in,
                              void* d_out, int out_size)
{
    const float* Up   = (const float*)d_in[0];
    const float* Uq   = (const float*)d_in[1];
    const float* Wp   = (const float*)d_in[2];
    const float* Wq   = (const float*)d_in[3];
    const float* Wv   = (const float*)d_in[4];
    const float* Wg   = (const float*)d_in[5];
    const float* Vm   = (const float*)d_in[6];
    const float* v0   = (const float*)d_in[7];
    const float* W_ih = (const float*)d_in[8];
    const float* W_hh = (const float*)d_in[9];
    const float* b_ih = (const float*)d_in[10];
    const float* b_hh = (const float*)d_in[11];
    float* out = (float*)d_out;

    cudaFuncSetAttribute(pqm_kernel, cudaFuncAttributeMaxDynamicSharedMemorySize, SMEM_BYTES);
    pqm_kernel<<<NBLK, NTHR, SMEM_BYTES>>>(Up, Uq, Wp, Wq, Wv, Wg, Vm, v0,
                                           W_ih, W_hh, b_ih, b_hh, out);
}

// round 10
// speedup vs baseline: 2.1076x; 1.0113x over previous
#include <cuda_runtime.h>
#include <cuda_fp16.h>

// ---------------- problem constants ----------------
#define NBLK 64
#define NTHR 1024
#define LPn  128
#define Bn   64

// packed-weight tile grids (16k x 8j tiles, B-fragment order)
#define WV_NCH  10
#define WV_NJT  20
#define WHH_NCH 10
#define WHH_NJT 58
#define WGC_NCH 10
#define WGC_NJT 75
#define WIH_NCH 40
#define WIH_NJT 58

// ---------------- device scratch ----------------
__device__ float d_WpE[150 * 152];
__device__ float d_WqE[150 * 152];
__device__ float d_WgU[600 * 152];
__device__ uint2 g_WvPk [WV_NCH  * WV_NJT  * 32];   // Wv^T    (k x j=150)
__device__ uint2 g_WhhPk[WHH_NCH * WHH_NJT * 32];   // W_hh^T  (k x j=450)
__device__ uint2 g_WgCPk[WGC_NCH * WGC_NJT * 32];   // WgC^T   (k x j=600)
__device__ uint2 g_WihPk[WIH_NCH * WIH_NJT * 32];   // W_ih^T  (k=600 x j=450)
__device__ float d_wup[Bn * LPn * 150];
__device__ float d_gu [Bn * LPn * 600];
__device__ unsigned g_flags[NBLK];
__device__ unsigned g_rel2;

// ---------------- smem layout (floats) ----------------
#define WUQ_S  0                      // Wuq fp32 [l*153+h]; P1: Up staging
#define UQH_S  19584                  // Uqt fp16 [l*152+d] = 9728 float slots
#define SCR    29312
#define V_S    (SCR + 0)              // 152 fp32 v
#define VB_S   (SCR + 152)            // 152 V row
#define U_S    (SCR + 304)            // 152 u
#define BSE_S  (SCR + 456)            // 152
#define CC_S   (SCR + 608)            // 152 fp32 cc
#define A_S    (SCR + 760)            // 128
#define GU_S   (SCR + 888)            // 600
#define GH_S   (SCR + 1488)           // 464
#define VP_S   (SCR + 1952)           // 80  half2 pairs of v (k pad 160)
#define CP2_S  (SCR + 2032)           // 80  half2 pairs of cc
#define RGP_S  (SCR + 2112)           // 320 half2 pairs of rg (k pad 640)
#define WVP_S  (SCR + 2432)           // 2 x 160 wv partials
#define BP_S   (SCR + 2752)           // 2 x 600 B partials
#define CPP_S  (SCR + 3952)           // 2 x 464 C partials
#define CCP_S  (SCR + 4880)           // 8 x 152 cc partials
#define AP_S   (SCR + 6096)           // 1024 s partials; P1 staging 9728 from here
#define SMEM_FL (SCR + 6096 + 9728)   // 45136 floats
#define SMEM_BYTES (SMEM_FL * 4)      // 180544 B

// ---------------- helpers ----------------
__device__ __forceinline__ float warp_max_all(float v) {
#pragma unroll
    for (int o = 16; o > 0; o >>= 1) v = fmaxf(v, __shfl_xor_sync(0xffffffffu, v, o));
    return v;
}
__device__ __forceinline__ float warp_sum_all(float v) {
#pragma unroll
    for (int o = 16; o > 0; o >>= 1) v += __shfl_xor_sync(0xffffffffu, v, o);
    return v;
}
__device__ __forceinline__ float fast_sig(float x) {
    return 1.0f / (1.0f + __expf(-x));
}
__device__ __forceinline__ float fast_tanh(float x) {
    float cx = fminf(fmaxf(x, -15.0f), 15.0f);
    float e  = __expf(2.0f * cx);
    return __fdividef(e - 1.0f, e + 1.0f);
}
__device__ __forceinline__ float tanh_fastest(float x) {
    float y;
    asm("tanh.approx.f32 %0, %1;" : "=f"(y) : "f"(x));
    return y;
}
__device__ __forceinline__ unsigned pack2(float x, float y) {
    __half2 h = __floats2half2_rn(x, y);
    return *reinterpret_cast<unsigned*>(&h);
}

// m16n8k16 f16 MMA, f32 accumulate. A rows 1-15 zero (GEMV): a-regs {xlow, 0, xhigh, 0}.
__device__ __forceinline__ void mma16816(float* d, unsigned a0, unsigned a1,
                                         unsigned b0, unsigned b1) {
    asm volatile(
        "mma.sync.aligned.m16n8k16.row.col.f32.f16.f16.f32 "
        "{%0,%1,%2,%3}, {%4,%5,%6,%7}, {%8,%9}, {%0,%1,%2,%3};"
        : "+f"(d[0]), "+f"(d[1]), "+f"(d[2]), "+f"(d[3])
        : "r"(a0), "r"(0u), "r"(a1), "r"(0u), "r"(b0), "r"(b1));
}

// GEMV tile loop: accumulate NT j-tiles over chunks [kc0,kc1).
template<int NT>
__device__ __forceinline__ void gemv_acc(float d[][4], const uint2* __restrict__ Wpk,
                                         int njt, int kc0, int kc1, int jt0,
                                         const unsigned* __restrict__ xp, int ln) {
    for (int kc = kc0; kc < kc1; kc++) {
        unsigned a0 = 0, a1 = 0;
        if (ln < 4) { a0 = xp[kc * 8 + ln]; a1 = xp[kc * 8 + 4 + ln]; }
        const uint2* wr = Wpk + (kc * njt + jt0) * 32 + ln;
#pragma unroll
        for (int t = 0; t < NT; t++) {
            uint2 bb = __ldg(&wr[t * 32]);
            mma16816(d[t], a0, a1, bb.x, bb.y);
        }
    }
}
template<int NT>
__device__ __forceinline__ void store_part(const float d[][4], float* dst,
                                           int jt0, int ln) {
    if (ln < 4) {
#pragma unroll
        for (int t = 0; t < NT; t++)
            *(float2*)(dst + (jt0 + t) * 8 + 2 * ln) = make_float2(d[t][0], d[t][1]);
    }
}

// Flag-array grid barrier (prologue only). Monotonic, atomic-free.
__device__ __forceinline__ void gsync(unsigned& gen) {
    __syncthreads();
    const unsigned target = gen + 1u;
    if (blockIdx.x == 0) {
        if (threadIdx.x < 32) {
            const int ln = threadIdx.x;
            if (ln == 0) *((volatile unsigned*)&g_flags[0]) = target;
            bool ok;
            do {
                unsigned f0, f1;
                asm volatile("ld.acquire.gpu.u32 %0, [%1];" : "=r"(f0) : "l"(&g_flags[ln]));
                asm volatile("ld.acquire.gpu.u32 %0, [%1];" : "=r"(f1) : "l"(&g_flags[ln + 32]));
                ok = (f0 >= target) & (f1 >= target);
            } while (!__all_sync(0xffffffffu, ok));
            if (ln == 0)
                asm volatile("st.release.gpu.u32 [%0], %1;" :: "l"(&g_rel2), "r"(target) : "memory");
        }
    } else {
        if (threadIdx.x == 0) {
            asm volatile("st.release.gpu.u32 [%0], %1;"
                         :: "l"(&g_flags[blockIdx.x]), "r"(target) : "memory");
            unsigned r;
            do {
                asm volatile("ld.acquire.gpu.u32 %0, [%1];" : "=r"(r) : "l"(&g_rel2));
            } while (r < target);
        }
    }
    gen = target;
    __syncthreads();
}

// ---------------- the persistent kernel: one block per batch ----------------
__global__ void __launch_bounds__(NTHR, 1) pqm_kernel(
    const float* __restrict__ Up, const float* __restrict__ Uq,
    const float* __restrict__ Wp, const float* __restrict__ Wq,
    const float* __restrict__ Wv, const float* __restrict__ Wg,
    const float* __restrict__ Vmat, const float* __restrict__ v0,
    const float* __restrict__ W_ih, const float* __restrict__ W_hh,
    const float* __restrict__ b_ih, const float* __restrict__ b_hh,
    float* __restrict__ out)
{
    extern __shared__ float sm[];
    __half* UQH = (__half*)(sm + UQH_S);
    unsigned* vpair  = (unsigned*)(sm + VP_S);
    unsigned* ccpair = (unsigned*)(sm + CP2_S);
    unsigned* rgpair = (unsigned*)(sm + RGP_S);
    const int tid = threadIdx.x;
    const int b   = blockIdx.x;
    const int w   = tid >> 5, ln = tid & 31;

    unsigned gen = *((volatile unsigned*)&g_rel2);

    // ======== P0: folds + packed fp16 B-fragment weight builds ========
    const int gid = b * NTHR + tid;
    const int gstride = NBLK * NTHR;
    for (int idx = gid; idx < 150 * 152; idx += gstride) {
        int h = idx / 152, d = idx - h * 152;
        d_WpE[idx] = (d < 150) ? Wp[h * 300 + d] + Wp[h * 300 + 150 + d] : 0.f;
        d_WqE[idx] = (d < 150) ? Wq[h * 300 + d] + Wq[h * 300 + 150 + d] : 0.f;
    }
    for (int idx = gid; idx < 600 * 152; idx += gstride) {
        int j = idx / 152, k = idx - j * 152;
        d_WgU[idx] = (k < 150) ? Wg[j * 600 + k] + Wg[j * 600 + 150 + k] : 0.f;
    }
    // Wv^T pack: W[k][j] = Wv[j*150+k], k<150, j<150
    for (int idx = gid; idx < WV_NCH * WV_NJT * 32; idx += gstride) {
        int lane = idx & 31, rest = idx >> 5;
        int jt = rest % WV_NJT, kc = rest / WV_NJT;
        int m = lane & 3, j = 8 * jt + (lane >> 2);
        int k0 = kc * 16 + 2 * m;
        float v00 = 0.f, v01 = 0.f, v10 = 0.f, v11 = 0.f;
        if (j < 150) {
            if (k0     < 150) v00 = Wv[j * 150 + k0];
            if (k0 + 1 < 150) v01 = Wv[j * 150 + k0 + 1];
            if (k0 + 8 < 150) v10 = Wv[j * 150 + k0 + 8];
            if (k0 + 9 < 150) v11 = Wv[j * 150 + k0 + 9];
        }
        g_WvPk[idx] = make_uint2(pack2(v00, v01), pack2(v10, v11));
    }
    // W_hh^T pack: W[k][j] = W_hh[j*150+k], k<150, j<450
    for (int idx = gid; idx < WHH_NCH * WHH_NJT * 32; idx += gstride) {
        int lane = idx & 31, rest = idx >> 5;
        int jt = rest % WHH_NJT, kc = rest / WHH_NJT;
        int m = lane & 3, j = 8 * jt + (lane >> 2);
        int k0 = kc * 16 + 2 * m;
        float v00 = 0.f, v01 = 0.f, v10 = 0.f, v11 = 0.f;
        if (j < 450) {
            if (k0     < 150) v00 = W_hh[j * 150 + k0];
            if (k0 + 1 < 150) v01 = W_hh[j * 150 + k0 + 1];
            if (k0 + 8 < 150) v10 = W_hh[j * 150 + k0 + 8];
            if (k0 + 9 < 150) v11 = W_hh[j * 150 + k0 + 9];
        }
        g_WhhPk[idx] = make_uint2(pack2(v00, v01), pack2(v10, v11));
    }
    // WgC^T pack: W[k][j] = Wg[j*600+300+k] + Wg[j*600+450+k], k<150, j<600
    for (int idx = gid; idx < WGC_NCH * WGC_NJT * 32; idx += gstride) {
        int lane = idx & 31, rest = idx >> 5;
        int jt = rest % WGC_NJT, kc = rest / WGC_NJT;
        int m = lane & 3, j = 8 * jt + (lane >> 2);
        int k0 = kc * 16 + 2 * m;
        float v00 = 0.f, v01 = 0.f, v10 = 0.f, v11 = 0.f;
        if (k0     < 150) v00 = Wg[j * 600 + 300 + k0]     + Wg[j * 600 + 450 + k0];
        if (k0 + 1 < 150) v01 = Wg[j * 600 + 300 + k0 + 1] + Wg[j * 600 + 450 + k0 + 1];
        if (k0 + 8 < 150) v10 = Wg[j * 600 + 300 + k0 + 8] + Wg[j * 600 + 450 + k0 + 8];
        if (k0 + 9 < 150) v11 = Wg[j * 600 + 300 + k0 + 9] + Wg[j * 600 + 450 + k0 + 9];
        g_WgCPk[idx] = make_uint2(pack2(v00, v01), pack2(v10, v11));
    }
    // W_ih^T pack: W[k][j] = W_ih[j*600+k], k<600, j<450
    for (int idx = gid; idx < WIH_NCH * WIH_NJT * 32; idx += gstride) {
        int lane = idx & 31, rest = idx >> 5;
        int jt = rest % WIH_NJT, kc = rest / WIH_NJT;
        int m = lane & 3, j = 8 * jt + (lane >> 2);
        int k0 = kc * 16 + 2 * m;
        float v00 = 0.f, v01 = 0.f, v10 = 0.f, v11 = 0.f;
        if (j < 450) {
            if (k0     < 600) v00 = W_ih[j * 600 + k0];
            if (k0 + 1 < 600) v01 = W_ih[j * 600 + k0 + 1];
            if (k0 + 8 < 600) v10 = W_ih[j * 600 + k0 + 8];
            if (k0 + 9 < 600) v11 = W_ih[j * 600 + k0 + 9];
        }
        g_WihPk[idx] = make_uint2(pack2(v00, v01), pack2(v10, v11));
    }
    gsync(gen);   // the ONLY grid barrier

    // ======== P1 (block-local): per-batch precompute ========
    {
        float* A = sm + WUQ_S;     // Up staging [i*152+k]
        for (int t = tid; t < 128 * 150; t += NTHR) {
            int ii = t / 150, k = t - ii * 150;
            A[ii * 152 + k] = Up[(ii * Bn + b) * 150 + k];
        }
        __syncthreads();
        for (int task = tid; task < 16 * 600; task += NTHR) {
            int j = task % 600, it = task / 600;
            float acc[8] = {0.f, 0.f, 0.f, 0.f, 0.f, 0.f, 0.f, 0.f};
            const float4* wr = (const float4*)(d_WgU + j * 152);
            for (int q = 0; q < 38; q++) {
                float4 w4 = wr[q];
#pragma unroll
                for (int ii = 0; ii < 8; ii++) {
                    const float* xr = A + (it * 8 + ii) * 152 + q * 4;
                    acc[ii] += w4.x * xr[0] + w4.y * xr[1] + w4.z * xr[2] + w4.w * xr[3];
                }
            }
#pragma unroll
            for (int ii = 0; ii < 8; ii++)
                d_gu[(b * LPn + it * 8 + ii) * 600 + j] = acc[ii];
        }
        for (int task = tid; task < 16 * 150; task += NTHR) {
            int h = task % 150, it = task / 150;
            float acc[8] = {0.f, 0.f, 0.f, 0.f, 0.f, 0.f, 0.f, 0.f};
            const float4* wr = (const float4*)(d_WpE + h * 152);
            for (int q = 0; q < 38; q++) {
                float4 w4 = wr[q];
#pragma unroll
                for (int ii = 0; ii < 8; ii++) {
                    const float* xr = A + (it * 8 + ii) * 152 + q * 4;
                    acc[ii] += w4.x * xr[0] + w4.y * xr[1] + w4.z * xr[2] + w4.w * xr[3];
                }
            }
#pragma unroll
            for (int ii = 0; ii < 8; ii++)
                d_wup[(b * LPn + it * 8 + ii) * 150 + h] = acc[ii];
        }
        __syncthreads();
        float* S2 = sm + AP_S;
        for (int ph = 0; ph < 2; ph++) {
            for (int t = tid; t < 64 * 150; t += NTHR) {
                int ll = t / 150, d = t - ll * 150;
                float vv = Uq[((ph * 64 + ll) * Bn + b) * 150 + d];
                S2[ll * 152 + d] = vv;
                UQH[(ph * 64 + ll) * 152 + d] = __float2half_rn(vv);
            }
            __syncthreads();
            for (int task = tid; task < 8 * 150; task += NTHR) {
                int h = task % 150, lt = task / 150;
                float acc[8] = {0.f, 0.f, 0.f, 0.f, 0.f, 0.f, 0.f, 0.f};
                const float4* wr = (const float4*)(d_WqE + h * 152);
                for (int q = 0; q < 38; q++) {
                    float4 w4 = wr[q];
#pragma unroll
                    for (int ii = 0; ii < 8; ii++) {
                        const float* xr = S2 + (lt * 8 + ii) * 152 + q * 4;
                        acc[ii] += w4.x * xr[0] + w4.y * xr[1] + w4.z * xr[2] + w4.w * xr[3];
                    }
                }
#pragma unroll
                for (int ii = 0; ii < 8; ii++)
                    sm[WUQ_S + (ph * 64 + lt * 8 + ii) * 153 + h] = acc[ii];
            }
            __syncthreads();
        }
        if (tid < 150) {
            sm[V_S + tid]  = v0[b * 150 + tid];
            sm[VB_S + tid] = Vmat[b * 150 + tid];
        }
        __syncthreads();
        // pair inits + pads
        if (tid < 80) {
            float x0 = (2 * tid     < 150) ? sm[V_S + 2 * tid]     : 0.f;
            float x1 = (2 * tid + 1 < 150) ? sm[V_S + 2 * tid + 1] : 0.f;
            vpair[tid] = pack2(x0, x1);
        }
        if (tid >= 128 && tid < 133) ccpair[75 + tid - 128] = 0u;
        if (tid >= 160 && tid < 180) rgpair[300 + tid - 160] = 0u;
    }
    __syncthreads();

    // ======== main scan: 128 steps, block-local ========
    for (int i = 0; i < LPn; i++) {
        // ---- Stage A: wv mma (w0-7) | gh mma (w8-23) | staging (w24-31) ----
        if (w < 8) {
            int kg = w >> 2, jgl = w & 3;
            float d[5][4];
#pragma unroll
            for (int t = 0; t < 5; t++) { d[t][0]=d[t][1]=d[t][2]=d[t][3]=0.f; }
            gemv_acc<5>(d, g_WvPk, WV_NJT, kg * 5, kg * 5 + 5, jgl * 5, vpair, ln);
            store_part<5>(d, sm + WVP_S + kg * 160, jgl * 5, ln);
        } else if (w < 24) {
            int wl = w - 8;
            int jt0, nt4 = (wl < 10);
            jt0 = nt4 ? wl * 4 : 40 + (wl - 10) * 3;
            if (nt4) {
                float d[4][4];
#pragma unroll
                for (int t = 0; t < 4; t++) { d[t][0]=d[t][1]=d[t][2]=d[t][3]=0.f; }
                gemv_acc<4>(d, g_WhhPk, WHH_NJT, 0, 10, jt0, vpair, ln);
                if (ln < 4) {
#pragma unroll
                    for (int t = 0; t < 4; t++) {
                        int j = (jt0 + t) * 8 + 2 * ln;
                        if (j < 450) {
                            sm[GH_S + j]     = d[t][0] + b_hh[j];
                            sm[GH_S + j + 1] = d[t][1] + b_hh[j + 1];
                        }
                    }
                }
            } else {
                float d[3][4];
#pragma unroll
                for (int t = 0; t < 3; t++) { d[t][0]=d[t][1]=d[t][2]=d[t][3]=0.f; }
                gemv_acc<3>(d, g_WhhPk, WHH_NJT, 0, 10, jt0, vpair, ln);
                if (ln < 4) {
#pragma unroll
                    for (int t = 0; t < 3; t++) {
                        int j = (jt0 + t) * 8 + 2 * ln;
                        if (j < 450) {
                            sm[GH_S + j]     = d[t][0] + b_hh[j];
                            sm[GH_S + j + 1] = d[t][1] + b_hh[j + 1];
                        }
                    }
                }
            }
        } else {
            for (int t = tid - 768; t < 900; t += 256) {
                if (t < 150)      sm[U_S + t]         = Up[(i * Bn + b) * 150 + t];
                else if (t < 300) sm[BSE_S + t - 150] = d_wup[(b * LPn + i) * 150 + t - 150];
                else              sm[GU_S + t - 300]  = d_gu[(b * LPn + i) * 600 + t - 300];
            }
        }
        __syncthreads();
        // ---- bse combine ----
        if (tid < 150) sm[BSE_S + tid] += sm[WVP_S + tid] + sm[WVP_S + 160 + tid];
        __syncthreads();
        // ---- S3: s[l] partials (128 l x 8 k-groups) ----
        {
            int l = tid & 127, g = tid >> 7;
            int k0 = (g * 150) >> 3, k1 = ((g + 1) * 150) >> 3;
            const float* wq = sm + WUQ_S + l * 153;
            float acc = 0.f;
#pragma unroll 10
            for (int k = k0; k < k1; k++)
                acc += tanh_fastest(sm[BSE_S + k] + wq[k]) * sm[VB_S + k];
            sm[AP_S + g * 128 + l] = acc;
        }
        __syncthreads();
        // ---- softmax (warp 0) ----
        if (w == 0) {
            float a0 = 0.f, a1 = 0.f, a2 = 0.f, a3 = 0.f;
#pragma unroll
            for (int g = 0; g < 8; g++) {
                const float* apg = sm + AP_S + g * 128;
                a0 += apg[ln]; a1 += apg[32 + ln]; a2 += apg[64 + ln]; a3 += apg[96 + ln];
            }
            float m = fmaxf(fmaxf(a0, a1), fmaxf(a2, a3));
            m = warp_max_all(m);
            float e0 = __expf(a0 - m), e1 = __expf(a1 - m);
            float e2 = __expf(a2 - m), e3 = __expf(a3 - m);
            float ssum = warp_sum_all(e0 + e1 + e2 + e3);
            float inv = __fdividef(1.0f, ssum);
            sm[A_S + ln] = e0 * inv; sm[A_S + 32 + ln] = e1 * inv;
            sm[A_S + 64 + ln] = e2 * inv; sm[A_S + 96 + ln] = e3 * inv;
        }
        __syncthreads();
        // ---- cc partials (8 l-groups x 150 d) ----
        for (int t = tid; t < 1200; t += NTHR) {
            int lq = t / 150, d = t - lq * 150;
            const __half* uq = UQH + lq * 16 * 152 + d;
            const float* av = sm + A_S + lq * 16;
            float acc = 0.f;
#pragma unroll
            for (int q = 0; q < 16; q++) acc += av[q] * __half2float(uq[q * 152]);
            sm[CCP_S + lq * 152 + d] = acc;
        }
        __syncthreads();
        // ---- cc combine (75 thr, 2 cols each) + pairs ----
        if (tid < 75) {
            float c0 = 0.f, c1 = 0.f;
            int d0 = 2 * tid, d1 = d0 + 1;
#pragma unroll
            for (int g = 0; g < 8; g++) {
                c0 += sm[CCP_S + g * 152 + d0];
                c1 += sm[CCP_S + g * 152 + d1];
            }
            sm[CC_S + d0] = c0; sm[CC_S + d1] = c1;
            ccpair[tid] = pack2(c0, c1);
        }
        __syncthreads();
        // ---- B mma (w0-29): bp = cc @ WgC^T partials ----
        if (w < 30) {
            int kg = w / 15, jgl = w - kg * 15;
            float d[5][4];
#pragma unroll
            for (int t = 0; t < 5; t++) { d[t][0]=d[t][1]=d[t][2]=d[t][3]=0.f; }
            gemv_acc<5>(d, g_WgCPk, WGC_NJT, kg * 5, kg * 5 + 5, jgl * 5, ccpair, ln);
            store_part<5>(d, sm + BP_S + kg * 600, jgl * 5, ln);
        }
        __syncthreads();
        // ---- B combine (300 thr, 2 j each): rg pairs ----
        if (tid < 300) {
            float r2[2];
#pragma unroll
            for (int s = 0; s < 2; s++) {
                int j = 2 * tid + s;
                float g = sm[GU_S + j] + sm[BP_S + j] + sm[BP_S + 600 + j];
                float sg = fast_sig(g);
                int km = (j < 150) ? j : (j < 300) ? j - 150 : (j < 450) ? j - 300 : j - 450;
                float rb = (j < 300) ? sm[U_S + km] : sm[CC_S + km];
                r2[s] = sg * rb;
            }
            rgpair[tid] = pack2(r2[0], r2[1]);
        }
        __syncthreads();
        // ---- C mma (all 32): cp = rg @ W_ih^T partials ----
        {
            int kg = w >> 4, jgl = w & 15;
            int nt4 = (jgl < 10);
            int jt0 = nt4 ? jgl * 4 : 40 + (jgl - 10) * 3;
            if (nt4) {
                float d[4][4];
#pragma unroll
                for (int t = 0; t < 4; t++) { d[t][0]=d[t][1]=d[t][2]=d[t][3]=0.f; }
                gemv_acc<4>(d, g_WihPk, WIH_NJT, kg * 20, kg * 20 + 20, jt0, rgpair, ln);
                store_part<4>(d, sm + CPP_S + kg * 464, jt0, ln);
            } else {
                float d[3][4];
#pragma unroll
                for (int t = 0; t < 3; t++) { d[t][0]=d[t][1]=d[t][2]=d[t][3]=0.f; }
                gemv_acc<3>(d, g_WihPk, WIH_NJT, kg * 20, kg * 20 + 20, jt0, rgpair, ln);
                store_part<3>(d, sm + CPP_S + kg * 464, jt0, ln);
            }
        }
        __syncthreads();
        // ---- GRU combine (75 thr, 2 h each) + v pairs ----
        if (tid < 75) {
            float hn2[2];
#pragma unroll
            for (int s = 0; s < 2; s++) {
                int h = 2 * tid + s;
                float ir  = b_ih[h]       + sm[CPP_S + h]       + sm[CPP_S + 464 + h];
                float iz  = b_ih[150 + h] + sm[CPP_S + 150 + h] + sm[CPP_S + 614 + h];
                float in_ = b_ih[300 + h] + sm[CPP_S + 300 + h] + sm[CPP_S + 764 + h];
                float r_ = fast_sig(ir + sm[GH_S + h]);
                float z_ = fast_sig(iz + sm[GH_S + 150 + h]);
                float n_ = fast_tanh(in_ + r_ * sm[GH_S + 300 + h]);
                float hnew = (1.0f - z_) * n_ + z_ * sm[V_S + h];
                out[(i * Bn + b) * 150 + h] = hnew;
                sm[V_S + h] = hnew;
                hn2[s] = hnew;
            }
            vpair[tid] = pack2(hn2[0], hn2[1]);
        }
        __syncthreads();
    }
}

// ---------------- launch ----------------
extern "C" void kernel_launch(void* const* d_in, const int* in_sizes, int n_in,
                              void* d_out, int out_size)
{
    const float* Up   = (const float*)d_in[0];
    const float* Uq   = (const float*)d_in[1];
    const float* Wp   = (const float*)d_in[2];
    const float* Wq   = (const float*)d_in[3];
    const float* Wv   = (const float*)d_in[4];
    const float* Wg   = (const float*)d_in[5];
    const float* Vm   = (const float*)d_in[6];
    const float* v0   = (const float*)d_in[7];
    const float* W_ih = (const float*)d_in[8];
    const float* W_hh = (const float*)d_in[9];
    const float* b_ih = (const float*)d_in[10];
    const float* b_hh = (const float*)d_in[11];
    float* out = (float*)d_out;

    cudaFuncSetAttribute(pqm_kernel, cudaFuncAttributeMaxDynamicSharedMemorySize, SMEM_BYTES);
    pqm_kernel<<<NBLK, NTHR, SMEM_BYTES>>>(Up, Uq, Wp, Wq, Wv, Wg, Vm, v0,
                                           W_ih, W_hh, b_ih, b_hh, out);
}